// round 15
// baseline (speedup 1.0000x reference)
#include <cuda_runtime.h>
#include <cuda_fp16.h>
#include <math.h>
#include <stdint.h>

// ---------------- problem constants ----------------
#define T_SEQ 1024
#define HID   2880
#define NH    64
#define KVH   8
#define DH    64
#define WIN   128
#define QKV_N 5120           // NH*DH + 2*KVH*DH
#define K_OFF 4096           // NH*DH
#define V_OFF 4608           // NH*DH + KVH*DH
#define ATT_N 4096           // NH*DH

#define KC1 180              // HID/16
#define KC2 256              // ATT_N/16
#define NBLK1 40             // QKV_N/128
#define NBLK2 23             // ceil(HID/128)

// ---------------- scratch (device globals; no allocation allowed) ----------------
__device__ float    g_qkv[(size_t)T_SEQ * QKV_N];     // un-roped qkv (fp32)
__device__ float    g_cos[T_SEQ * 32];
__device__ float    g_sin[T_SEQ * 32];
__device__ unsigned g_Ap1[(size_t)8 * KC1 * 1024];
__device__ unsigned g_Ap2[(size_t)8 * KC2 * 1024];
__device__ unsigned g_Bp1[(size_t)NBLK1 * KC1 * 1024];
__device__ unsigned g_Bp2[(size_t)NBLK2 * KC2 * 1024];

// ================= fragment-permuted fp16 layouts =================
// A element (row, k):  lane=(r16%8)*4+(kin%8)/2 ; j=(r16/8)+2*(kin/8)
// B element (k, n):    lane=(n%8)*4+(kin%8)/2 ; j=kin/8

// ---------------- weight conversion: coalesced smem-tiled ----------------
__global__ void __launch_bounds__(256)
convB_kernel(const float* __restrict__ W, unsigned* __restrict__ Bp,
             int K, int N, int KC)
{
    __shared__ float tile[16][132];
    const int nblk = blockIdx.x;
    const int kc = blockIdx.y;
    const int tid = threadIdx.x;

    {
        const int r = tid >> 4;
        const int q = tid & 15;
        const int gk = kc * 16 + r;
        const int gn = nblk * 128 + q * 8;
        float4 v0 = make_float4(0.f, 0.f, 0.f, 0.f);
        float4 v1 = make_float4(0.f, 0.f, 0.f, 0.f);
        if (gn < N)
            v0 = *reinterpret_cast<const float4*>(&W[(size_t)gk * N + gn]);
        if (gn + 4 < N)
            v1 = *reinterpret_cast<const float4*>(&W[(size_t)gk * N + gn + 4]);
        *reinterpret_cast<float4*>(&tile[r][q * 8]) = v0;
        *reinterpret_cast<float4*>(&tile[r][q * 8 + 4]) = v1;
    }
    __syncthreads();

    unsigned ov[4];
#pragma unroll
    for (int c = 0; c < 4; c++) {
        const int o = tid * 4 + c;
        const int nt = o >> 6, rem = o & 63, l = rem >> 1, j = rem & 1;
        const int n_loc = nt * 8 + (l >> 2);
        const int k_loc = (l & 3) * 2 + (j << 3);
        __half2 h = __floats2half2_rn(tile[k_loc][n_loc], tile[k_loc + 1][n_loc]);
        ov[c] = *reinterpret_cast<unsigned*>(&h);
    }
    *reinterpret_cast<uint4*>(&Bp[(size_t)(nblk * KC + kc) * 1024 + tid * 4]) =
        make_uint4(ov[0], ov[1], ov[2], ov[3]);
}

// ---------------- RMSNorm fused with convA (emits permuted fp16 A for gemm1) ----------------
__global__ void __launch_bounds__(256)
rmsnorm_convA_kernel(const float* __restrict__ x,
                     const float* __restrict__ scale,
                     unsigned* __restrict__ Ap)
{
    const int t = blockIdx.x;
    const float4* xr = reinterpret_cast<const float4*>(x + (size_t)t * HID);
    float ss = 0.f;
    for (int i = threadIdx.x; i < HID / 4; i += 256) {
        float4 v = xr[i];
        ss += v.x * v.x + v.y * v.y + v.z * v.z + v.w * v.w;
    }
    __shared__ float red[8];
    for (int off = 16; off; off >>= 1) ss += __shfl_xor_sync(0xffffffffu, ss, off);
    if ((threadIdx.x & 31) == 0) red[threadIdx.x >> 5] = ss;
    __syncthreads();
    if (threadIdx.x < 32) {
        float v = (threadIdx.x < 8) ? red[threadIdx.x] : 0.f;
        for (int off = 4; off; off >>= 1) v += __shfl_xor_sync(0xffffffffu, v, off);
        if (threadIdx.x == 0) red[0] = v;
    }
    __syncthreads();
    const float r = rsqrtf(red[0] / (float)HID + 1e-5f);

    const int mblk = t >> 7, mt = (t >> 4) & 7;
    const int lbase = (t & 7) * 4, jbase = (t >> 3) & 1;
    const float2* x2 = reinterpret_cast<const float2*>(x + (size_t)t * HID);
    const float2* s2 = reinterpret_cast<const float2*>(scale);
    for (int idx = threadIdx.x; idx < HID / 2; idx += 256) {
        const int k = idx * 2, kc = k >> 4, kin = k & 15;
        const int l = lbase + ((kin & 7) >> 1);
        const int j = jbase + ((kin >> 3) << 1);
        float2 v = x2[idx], sc = s2[idx];
        __half2 h = __floats2half2_rn(v.x * r * sc.x, v.y * r * sc.y);
        Ap[(((size_t)(mblk * KC1 + kc) * 8 + mt) * 32 + l) * 4 + j] =
            *reinterpret_cast<unsigned*>(&h);
    }
}

// ---------------- YaRN RoPE cos/sin table ----------------
__global__ void rope_table_kernel(const int* __restrict__ positions,
                                  float* __restrict__ gcos,
                                  float* __restrict__ gsin)
{
    const int t = blockIdx.x;
    const int i = threadIdx.x;  // 0..31
    const double pos = (double)positions[t];
    const double TWO_PI = 6.283185307179586476925286766559;
    const double BASE = 150000.0;
    const double freq = pow(BASE, (2.0 * i) / 64.0);
    const double conc = 0.1 * log(32.0) + 1.0;
    const double lo = 32.0 * log(4096.0 / (32.0 * TWO_PI)) / log(BASE);
    const double hi = 32.0 * log(4096.0 / (1.0 * TWO_PI)) / log(BASE);
    const double interp = 1.0 / (32.0 * freq);
    const double extrap = 1.0 / freq;
    double ramp = ((double)i - lo) / (hi - lo);
    ramp = fmin(fmax(ramp, 0.0), 1.0);
    const double mask = 1.0 - ramp;
    const double inv = interp * (1.0 - mask) + extrap * mask;
    const double ang = pos * inv;
    gcos[t * 32 + i] = (float)(cos(ang) * conc);
    gsin[t * 32 + i] = (float)(sin(ang) * conc);
}

// ================= fp16 mma.sync GEMM, 128x64 tile, 3-stage cp.async =================
// 128 threads (4 warps, 2x2), warp tile 64x32, m16n8k16. 5 CTAs/SM.
__device__ __forceinline__ void cp16(uint32_t dst, const void* src)
{
    asm volatile("cp.async.cg.shared.global [%0], [%1], 16;"
                 :: "r"(dst), "l"(src) : "memory");
}
#define CP_COMMIT() asm volatile("cp.async.commit_group;" ::: "memory")
#define CP_WAIT1()  asm volatile("cp.async.wait_group 1;" ::: "memory")

#define MMA_F16(d, a, b) \
    asm volatile("mma.sync.aligned.m16n8k16.row.col.f32.f16.f16.f32 " \
                 "{%0,%1,%2,%3},{%4,%5,%6,%7},{%8,%9},{%0,%1,%2,%3};" \
                 : "+f"((d)[0]), "+f"((d)[1]), "+f"((d)[2]), "+f"((d)[3]) \
                 : "r"((a).x), "r"((a).y), "r"((a).z), "r"((a).w), \
                   "r"((b).x), "r"((b).y))

#define HSTAGES 3
// per stage: A 2048 u32 (8KB) + B 1024 u32 (4KB) = 12KB
#define HGEMM_SMEM (HSTAGES * 3072 * 4)

__global__ void __launch_bounds__(128, 5)
hgemm_kernel(int M, int N, int K,
             const unsigned* __restrict__ Ap,
             const unsigned* __restrict__ Bp,
             const float* __restrict__ bias,
             const float* __restrict__ resid,
             float* __restrict__ C)
{
    extern __shared__ unsigned hsm[];

    const int KC = K >> 4;
    const int tid = threadIdx.x, lane = tid & 31, wid = tid >> 5;
    const int wm = wid >> 1, wn = wid & 1;
    const int mblk = blockIdx.y;
    const int nb64 = blockIdx.x;
    const int nb128 = nb64 >> 1, nhalf = nb64 & 1;
    const unsigned* Abase = Ap + (size_t)mblk * KC * 1024;
    const unsigned* Bbase = Bp + (size_t)nb128 * KC * 1024 + nhalf * 512;

    float acc[4][4][4];
#pragma unroll
    for (int i = 0; i < 4; i++)
#pragma unroll
        for (int j = 0; j < 4; j++)
#pragma unroll
            for (int q = 0; q < 4; q++) acc[i][j][q] = 0.f;

    const uint32_t sbase = (uint32_t)__cvta_generic_to_shared(hsm);
    const int nch = K / 32;

#define ISSUE_COPY(ch, s)                                                     \
    do {                                                                      \
        const unsigned* asrc = Abase + (size_t)(ch) * 2048;                   \
        uint32_t da = sbase + (s) * 12288;                                    \
        uint32_t db = da + 8192;                                              \
        cp16(da + tid * 16, asrc + tid * 4);                                  \
        cp16(da + (tid + 128) * 16, asrc + (tid + 128) * 4);                  \
        cp16(da + (tid + 256) * 16, asrc + (tid + 256) * 4);                  \
        cp16(da + (tid + 384) * 16, asrc + (tid + 384) * 4);                  \
        cp16(db + tid * 16,                                                   \
             Bbase + (size_t)(2 * (ch)) * 1024 + tid * 4);                    \
        cp16(db + 2048 + tid * 16,                                            \
             Bbase + (size_t)(2 * (ch) + 1) * 1024 + tid * 4);                \
    } while (0)

    ISSUE_COPY(0, 0); CP_COMMIT();
    ISSUE_COPY(1, 1); CP_COMMIT();

    for (int ch = 0; ch < nch; ch++) {
        CP_WAIT1();
        __syncthreads();

        if (ch + 2 < nch) {
            const int s2 = (ch + 2) % 3;
            ISSUE_COPY(ch + 2, s2);
        }
        CP_COMMIT();

        const int st = ch % 3;
        const unsigned* Ast = hsm + (size_t)st * 3072;
        const unsigned* Bst = Ast + 2048;
#pragma unroll
        for (int ks = 0; ks < 2; ks++) {
            uint4 af[4];
            uint2 bf[4];
            const unsigned* ab = &Ast[ks * 1024 + wm * 512 + lane * 4];
            const unsigned* bb = &Bst[ks * 512 + wn * 256 + lane * 2];
#pragma unroll
            for (int mt = 0; mt < 4; mt++)
                af[mt] = *reinterpret_cast<const uint4*>(ab + mt * 128);
#pragma unroll
            for (int nt = 0; nt < 4; nt++)
                bf[nt] = *reinterpret_cast<const uint2*>(bb + nt * 64);
#pragma unroll
            for (int mt = 0; mt < 4; mt++)
#pragma unroll
                for (int nt = 0; nt < 4; nt++)
                    MMA_F16(acc[mt][nt], af[mt], bf[nt]);
        }
    }

    const int m0 = mblk * 128 + wm * 64;
    const int n0 = nb64 * 64 + wn * 32;
#pragma unroll
    for (int mt = 0; mt < 4; mt++) {
        const int r = m0 + mt * 16 + (lane >> 2);
#pragma unroll
        for (int nt = 0; nt < 4; nt++) {
            const int c = n0 + nt * 8 + ((lane & 3) << 1);
            if (c < N) {
                const float2 b = *reinterpret_cast<const float2*>(&bias[c]);
                float2 o0 = make_float2(acc[mt][nt][0] + b.x, acc[mt][nt][1] + b.y);
                float2 o1 = make_float2(acc[mt][nt][2] + b.x, acc[mt][nt][3] + b.y);
                const size_t i0 = (size_t)r * N + c;
                const size_t i1 = i0 + (size_t)8 * N;
                if (resid) {
                    float2 e0 = *reinterpret_cast<const float2*>(&resid[i0]);
                    float2 e1 = *reinterpret_cast<const float2*>(&resid[i1]);
                    o0.x += e0.x; o0.y += e0.y;
                    o1.x += e1.x; o1.y += e1.y;
                }
                *reinterpret_cast<float2*>(&C[i0]) = o0;
                *reinterpret_cast<float2*>(&C[i1]) = o1;
            }
        }
    }
}

// ================= tensor-core sliding-window attention =================
// Online softmax over two key chunks (80 + 64) to cut register pressure.
// grid (kvh, qtile): 16 queries/block, 144-key window, 256 thr, warp = head.
// k0 = qt0 - 128; allowed for query q: jl > q && jl <= q+128.
#define TQ 16
#define NKEY 144
#define QPAD 72              // halves per Q/K row
#define VPAD 152             // halves per Vt row
#define ATTN_SMEM ((128 * QPAD + NKEY * QPAD + 64 * VPAD) * 2)

// one chunk: NT n8-score-tiles starting at key offset KB (NT even)
template<int NT, int KB>
__device__ __forceinline__ void attn_chunk(
    const __half* __restrict__ Ks, const __half* __restrict__ Vt,
    const uint4 af[4], int lane, int k0, int q_a, int q_b,
    float& Ma, float& la, float& Mb, float& lb, float (&oacc)[8][4])
{
    float sacc[NT][4];
#pragma unroll
    for (int nt = 0; nt < NT; nt++)
#pragma unroll
        for (int c = 0; c < 4; c++) sacc[nt][c] = 0.f;

#pragma unroll
    for (int nt = 0; nt < NT; nt++) {
        const __half* krow = &Ks[(KB + nt * 8 + (lane >> 2)) * QPAD];
#pragma unroll
        for (int kt = 0; kt < 4; kt++) {
            uint2 b;
            const int col = kt * 16 + ((lane & 3) << 1);
            b.x = *reinterpret_cast<const unsigned*>(&krow[col]);
            b.y = *reinterpret_cast<const unsigned*>(&krow[col + 8]);
            MMA_F16(sacc[nt], af[kt], b);
        }
    }

    // mask + chunk max
    float cma = -1e30f, cmb = -1e30f;
#pragma unroll
    for (int nt = 0; nt < NT; nt++) {
#pragma unroll
        for (int c = 0; c < 2; c++) {
            const int jl = KB + nt * 8 + ((lane & 3) << 1) + c;
            const bool in0 = (k0 + jl >= 0);
            const bool oka = in0 && (jl > q_a) && (jl <= q_a + 128);
            const bool okb = in0 && (jl > q_b) && (jl <= q_b + 128);
            const float va = oka ? sacc[nt][c] * 0.125f : -1e30f;
            const float vb = okb ? sacc[nt][c + 2] * 0.125f : -1e30f;
            sacc[nt][c] = va; sacc[nt][c + 2] = vb;
            cma = fmaxf(cma, va); cmb = fmaxf(cmb, vb);
        }
    }
    cma = fmaxf(cma, __shfl_xor_sync(0xffffffffu, cma, 1));
    cma = fmaxf(cma, __shfl_xor_sync(0xffffffffu, cma, 2));
    cmb = fmaxf(cmb, __shfl_xor_sync(0xffffffffu, cmb, 1));
    cmb = fmaxf(cmb, __shfl_xor_sync(0xffffffffu, cmb, 2));

    const float nMa = fmaxf(Ma, cma), nMb = fmaxf(Mb, cmb);
    const float fa = __expf(Ma - nMa), fb = __expf(Mb - nMb);
    Ma = nMa; Mb = nMb;

    unsigned pha[NT], phb[NT];
    float psa = 0.f, psb = 0.f;
#pragma unroll
    for (int nt = 0; nt < NT; nt++) {
        const float p0 = __expf(sacc[nt][0] - Ma);
        const float p1 = __expf(sacc[nt][1] - Ma);
        const float p2 = __expf(sacc[nt][2] - Mb);
        const float p3 = __expf(sacc[nt][3] - Mb);
        psa += p0 + p1; psb += p2 + p3;
        __half2 ha = __floats2half2_rn(p0, p1);
        __half2 hb = __floats2half2_rn(p2, p3);
        pha[nt] = *reinterpret_cast<unsigned*>(&ha);
        phb[nt] = *reinterpret_cast<unsigned*>(&hb);
    }
    psa += __shfl_xor_sync(0xffffffffu, psa, 1);
    psa += __shfl_xor_sync(0xffffffffu, psa, 2);
    psb += __shfl_xor_sync(0xffffffffu, psb, 1);
    psb += __shfl_xor_sync(0xffffffffu, psb, 2);
    la = la * fa + psa;
    lb = lb * fb + psb;

#pragma unroll
    for (int nt = 0; nt < 8; nt++) {
        oacc[nt][0] *= fa; oacc[nt][1] *= fa;
        oacc[nt][2] *= fb; oacc[nt][3] *= fb;
    }

#pragma unroll
    for (int kt = 0; kt < NT / 2; kt++) {
        uint4 a;
        a.x = pha[2 * kt];
        a.y = phb[2 * kt];
        a.z = pha[2 * kt + 1];
        a.w = phb[2 * kt + 1];
        const int kcol = KB + kt * 16 + ((lane & 3) << 1);
#pragma unroll
        for (int nt = 0; nt < 8; nt++) {
            const __half* vrow = &Vt[(nt * 8 + (lane >> 2)) * VPAD];
            uint2 b;
            b.x = *reinterpret_cast<const unsigned*>(&vrow[kcol]);
            b.y = *reinterpret_cast<const unsigned*>(&vrow[kcol + 8]);
            MMA_F16(oacc[nt], a, b);
        }
    }
}

__global__ void __launch_bounds__(256, 2)
attn_mma_kernel(const float* __restrict__ qkv,
                const float* __restrict__ gcos,
                const float* __restrict__ gsin,
                const float* __restrict__ sinks,
                unsigned* __restrict__ Ap2)
{
    extern __shared__ __half asmem[];
    __half* Qs = asmem;                       // [128][QPAD]
    __half* Ks = Qs + 128 * QPAD;             // [NKEY][QPAD]
    __half* Vt = Ks + NKEY * QPAD;            // [64][VPAD]

    const int kvh = blockIdx.x;
    const int qt0 = blockIdx.y * TQ;
    const int k0 = qt0 - WIN;
    const int tid = threadIdx.x;
    const int lane = tid & 31;
    const int wid = tid >> 5;                 // head within group

    // ---- load Q with fused RoPE ----
#pragma unroll
    for (int it = 0; it < 4; it++) {
        const int idx = tid + it * 256;       // 0..1023
        const int row = idx >> 3;
        const int c4 = (idx & 7) * 4;
        const int h = row >> 4, q = row & 15;
        const int t = qt0 + q;
        const float* src = &qkv[(size_t)t * QKV_N + (size_t)(kvh * 8 + h) * DH];
        float4 x1 = *reinterpret_cast<const float4*>(&src[c4]);
        float4 x2 = *reinterpret_cast<const float4*>(&src[c4 + 32]);
        float4 cs = *reinterpret_cast<const float4*>(&gcos[t * 32 + c4]);
        float4 sn = *reinterpret_cast<const float4*>(&gsin[t * 32 + c4]);
        __half* d1 = &Qs[row * QPAD + c4];
        __half* d2 = d1 + 32;
        d1[0] = __float2half_rn(x1.x * cs.x - x2.x * sn.x);
        d1[1] = __float2half_rn(x1.y * cs.y - x2.y * sn.y);
        d1[2] = __float2half_rn(x1.z * cs.z - x2.z * sn.z);
        d1[3] = __float2half_rn(x1.w * cs.w - x2.w * sn.w);
        d2[0] = __float2half_rn(x2.x * cs.x + x1.x * sn.x);
        d2[1] = __float2half_rn(x2.y * cs.y + x1.y * sn.y);
        d2[2] = __float2half_rn(x2.z * cs.z + x1.z * sn.z);
        d2[3] = __float2half_rn(x2.w * cs.w + x1.w * sn.w);
    }
    // ---- load K with fused RoPE ----
#pragma unroll
    for (int it = 0; it < 5; it++) {
        const int idx = tid + it * 256;       // 0..1151
        if (idx < NKEY * 8) {
            const int kk = idx >> 3;
            const int c4 = (idx & 7) * 4;
            const int j = k0 + kk;
            __half* d1 = &Ks[kk * QPAD + c4];
            __half* d2 = d1 + 32;
            if (j >= 0) {
                const float* src = &qkv[(size_t)j * QKV_N + K_OFF + (size_t)kvh * DH];
                float4 x1 = *reinterpret_cast<const float4*>(&src[c4]);
                float4 x2 = *reinterpret_cast<const float4*>(&src[c4 + 32]);
                float4 cs = *reinterpret_cast<const float4*>(&gcos[j * 32 + c4]);
                float4 sn = *reinterpret_cast<const float4*>(&gsin[j * 32 + c4]);
                d1[0] = __float2half_rn(x1.x * cs.x - x2.x * sn.x);
                d1[1] = __float2half_rn(x1.y * cs.y - x2.y * sn.y);
                d1[2] = __float2half_rn(x1.z * cs.z - x2.z * sn.z);
                d1[3] = __float2half_rn(x1.w * cs.w - x2.w * sn.w);
                d2[0] = __float2half_rn(x2.x * cs.x + x1.x * sn.x);
                d2[1] = __float2half_rn(x2.y * cs.y + x1.y * sn.y);
                d2[2] = __float2half_rn(x2.z * cs.z + x1.z * sn.z);
                d2[3] = __float2half_rn(x2.w * cs.w + x1.w * sn.w);
            } else {
                const __half z = __float2half_rn(0.f);
                d1[0] = z; d1[1] = z; d1[2] = z; d1[3] = z;
                d2[0] = z; d2[1] = z; d2[2] = z; d2[3] = z;
            }
        }
    }
    // ---- load V transposed: Vt[d][key] ----
#pragma unroll
    for (int it = 0; it < 9; it++) {
        const int idx = tid + it * 256;
        const int kk = idx >> 4;
        const int c4 = (idx & 15) * 4;
        const int j = k0 + kk;
        float4 v = (j >= 0)
            ? *reinterpret_cast<const float4*>(
                  &qkv[(size_t)j * QKV_N + V_OFF + (size_t)kvh * DH + c4])
            : make_float4(0.f, 0.f, 0.f, 0.f);
        Vt[(c4 + 0) * VPAD + kk] = __float2half_rn(v.x);
        Vt[(c4 + 1) * VPAD + kk] = __float2half_rn(v.y);
        Vt[(c4 + 2) * VPAD + kk] = __float2half_rn(v.z);
        Vt[(c4 + 3) * VPAD + kk] = __float2half_rn(v.w);
    }
    __syncthreads();

    // ---- Q fragments ----
    const __half* qrow = &Qs[(wid * 16 + (lane >> 2)) * QPAD];
    uint4 af[4];
#pragma unroll
    for (int kt = 0; kt < 4; kt++) {
        const int col = kt * 16 + ((lane & 3) << 1);
        af[kt].x = *reinterpret_cast<const unsigned*>(&qrow[col]);
        af[kt].y = *reinterpret_cast<const unsigned*>(&qrow[8 * QPAD + col]);
        af[kt].z = *reinterpret_cast<const unsigned*>(&qrow[col + 8]);
        af[kt].w = *reinterpret_cast<const unsigned*>(&qrow[8 * QPAD + col + 8]);
    }

    const int q_a = lane >> 2, q_b = q_a + 8;
    float Ma = -1e30f, Mb = -1e30f, la = 0.f, lb = 0.f;
    float oacc[8][4];
#pragma unroll
    for (int nt = 0; nt < 8; nt++)
#pragma unroll
        for (int c = 0; c < 4; c++) oacc[nt][c] = 0.f;

    attn_chunk<10, 0>(Ks, Vt, af, lane, k0, q_a, q_b, Ma, la, Mb, lb, oacc);
    attn_chunk<8, 80>(Ks, Vt, af, lane, k0, q_a, q_b, Ma, la, Mb, lb, oacc);

    // ---- fold sink, normalize ----
    const float sink = sinks[kvh * 8 + wid];
    const float FMa = fmaxf(Ma, sink), FMb = fmaxf(Mb, sink);
    const float ffa = __expf(Ma - FMa), ffb = __expf(Mb - FMb);
    const float lfa = la * ffa + __expf(sink - FMa);
    const float lfb = lb * ffb + __expf(sink - FMb);
    const float inva = ffa / lfa, invb = ffb / lfb;

    // ---- epilogue: emit permuted fp16 A for gemm2 directly ----
    const int mblk = qt0 >> 7, mt = (qt0 >> 4) & 7;
    const int head = kvh * 8 + wid;
#pragma unroll
    for (int kcp = 0; kcp < 4; kcp++) {
        const int nt0 = 2 * kcp, nt1 = 2 * kcp + 1;
        __half2 h0 = __floats2half2_rn(oacc[nt0][0] * inva, oacc[nt0][1] * inva);
        __half2 h1 = __floats2half2_rn(oacc[nt0][2] * invb, oacc[nt0][3] * invb);
        __half2 h2 = __floats2half2_rn(oacc[nt1][0] * inva, oacc[nt1][1] * inva);
        __half2 h3 = __floats2half2_rn(oacc[nt1][2] * invb, oacc[nt1][3] * invb);
        const int kc = head * 4 + kcp;
        const size_t base = (((size_t)(mblk * KC2 + kc) * 8 + mt) * 32 + lane) * 4;
        *reinterpret_cast<uint4*>(&Ap2[base]) =
            make_uint4(*reinterpret_cast<unsigned*>(&h0),
                       *reinterpret_cast<unsigned*>(&h1),
                       *reinterpret_cast<unsigned*>(&h2),
                       *reinterpret_cast<unsigned*>(&h3));
    }
}

// ---------------- launch ----------------
extern "C" void kernel_launch(void* const* d_in, const int* in_sizes, int n_in,
                              void* d_out, int out_size)
{
    const float* hidden     = (const float*)d_in[0];
    const int*   positions  = (const int*)d_in[1];
    const float* norm_scale = (const float*)d_in[2];
    const float* w_qkv      = (const float*)d_in[3];
    const float* b_qkv      = (const float*)d_in[4];
    const float* w_out      = (const float*)d_in[5];
    const float* b_out      = (const float*)d_in[6];
    const float* sinks      = (const float*)d_in[7];
    float* out = (float*)d_out;

    float *qkv, *gcos, *gsin;
    unsigned *Ap1, *Ap2, *Bp1, *Bp2;
    cudaGetSymbolAddress((void**)&qkv, g_qkv);
    cudaGetSymbolAddress((void**)&gcos, g_cos);
    cudaGetSymbolAddress((void**)&gsin, g_sin);
    cudaGetSymbolAddress((void**)&Ap1, g_Ap1);
    cudaGetSymbolAddress((void**)&Ap2, g_Ap2);
    cudaGetSymbolAddress((void**)&Bp1, g_Bp1);
    cudaGetSymbolAddress((void**)&Bp2, g_Bp2);

    cudaFuncSetAttribute(hgemm_kernel,
                         cudaFuncAttributeMaxDynamicSharedMemorySize, HGEMM_SMEM);
    cudaFuncSetAttribute(attn_mma_kernel,
                         cudaFuncAttributeMaxDynamicSharedMemorySize, ATTN_SMEM);

    // 1: rope table
    rope_table_kernel<<<T_SEQ, 32>>>(positions, gcos, gsin);
    // 2: convert w_qkv
    convB_kernel<<<dim3(NBLK1, KC1), 256>>>(w_qkv, Bp1, HID, QKV_N, KC1);
    // 3: rmsnorm + convert A1
    rmsnorm_convA_kernel<<<T_SEQ, 256>>>(hidden, norm_scale, Ap1);
    // 4 (profiled slot): qkv GEMM (M=1024, N=5120, K=2880), 128x64 tiles
    hgemm_kernel<<<dim3(QKV_N / 64, T_SEQ / 128), 128, HGEMM_SMEM>>>(
        T_SEQ, QKV_N, HID, Ap1, Bp1, b_qkv, nullptr, qkv);
    // 5: attention (fused rope + online softmax + permuted fp16 output)
    attn_mma_kernel<<<dim3(KVH, T_SEQ / TQ), 256, ATTN_SMEM>>>(
        qkv, gcos, gsin, sinks, Ap2);
    // 6: convert w_out
    convB_kernel<<<dim3(NBLK2, KC2), 256>>>(w_out, Bp2, ATT_N, HID, KC2);
    // 7: out GEMM + residual (M=1024, N=2880, K=4096), 128x64 tiles
    hgemm_kernel<<<dim3(HID / 64, T_SEQ / 128), 128, HGEMM_SMEM>>>(
        T_SEQ, HID, ATT_N, Ap2, Bp2, b_out, hidden, out);
}

// round 17
// speedup vs baseline: 1.5252x; 1.5252x over previous
#include <cuda_runtime.h>
#include <cuda_fp16.h>
#include <math.h>
#include <stdint.h>

// ---------------- problem constants ----------------
#define T_SEQ 1024
#define HID   2880
#define NH    64
#define KVH   8
#define DH    64
#define WIN   128
#define QKV_N 5120           // NH*DH + 2*KVH*DH
#define K_OFF 4096           // NH*DH
#define V_OFF 4608           // NH*DH + KVH*DH
#define ATT_N 4096           // NH*DH

#define KC1 180              // HID/16
#define KC2 256              // ATT_N/16
#define NBLK1 40             // QKV_N/128
#define NBLK2 23             // ceil(HID/128)

// ---------------- scratch (device globals; no allocation allowed) ----------------
__device__ float    g_qkv[(size_t)T_SEQ * QKV_N];     // un-roped qkv (fp32)
__device__ float    g_cos[T_SEQ * 32];
__device__ float    g_sin[T_SEQ * 32];
__device__ unsigned g_Ap1[(size_t)8 * KC1 * 1024];
__device__ unsigned g_Ap2[(size_t)8 * KC2 * 1024];
__device__ unsigned g_Bp1[(size_t)NBLK1 * KC1 * 1024];
__device__ unsigned g_Bp2[(size_t)NBLK2 * KC2 * 1024];

// ================= fragment-permuted fp16 layouts =================
// A element (row, k):  lane=(r16%8)*4+(kin%8)/2 ; j=(r16/8)+2*(kin/8)
// B element (k, n):    lane=(n%8)*4+(kin%8)/2 ; j=kin/8

// ---------------- weight conversion: coalesced smem-tiled ----------------
__global__ void __launch_bounds__(256)
convB_kernel(const float* __restrict__ W, unsigned* __restrict__ Bp,
             int K, int N, int KC)
{
    __shared__ float tile[16][132];
    const int nblk = blockIdx.x;
    const int kc = blockIdx.y;
    const int tid = threadIdx.x;

    {
        const int r = tid >> 4;
        const int q = tid & 15;
        const int gk = kc * 16 + r;
        const int gn = nblk * 128 + q * 8;
        float4 v0 = make_float4(0.f, 0.f, 0.f, 0.f);
        float4 v1 = make_float4(0.f, 0.f, 0.f, 0.f);
        if (gn < N)
            v0 = *reinterpret_cast<const float4*>(&W[(size_t)gk * N + gn]);
        if (gn + 4 < N)
            v1 = *reinterpret_cast<const float4*>(&W[(size_t)gk * N + gn + 4]);
        *reinterpret_cast<float4*>(&tile[r][q * 8]) = v0;
        *reinterpret_cast<float4*>(&tile[r][q * 8 + 4]) = v1;
    }
    __syncthreads();

    unsigned ov[4];
#pragma unroll
    for (int c = 0; c < 4; c++) {
        const int o = tid * 4 + c;
        const int nt = o >> 6, rem = o & 63, l = rem >> 1, j = rem & 1;
        const int n_loc = nt * 8 + (l >> 2);
        const int k_loc = (l & 3) * 2 + (j << 3);
        __half2 h = __floats2half2_rn(tile[k_loc][n_loc], tile[k_loc + 1][n_loc]);
        ov[c] = *reinterpret_cast<unsigned*>(&h);
    }
    *reinterpret_cast<uint4*>(&Bp[(size_t)(nblk * KC + kc) * 1024 + tid * 4]) =
        make_uint4(ov[0], ov[1], ov[2], ov[3]);
}

// ---------------- RMSNorm fused with convA (emits permuted fp16 A for gemm1) ----------------
__global__ void __launch_bounds__(256)
rmsnorm_convA_kernel(const float* __restrict__ x,
                     const float* __restrict__ scale,
                     unsigned* __restrict__ Ap)
{
    const int t = blockIdx.x;
    const float4* xr = reinterpret_cast<const float4*>(x + (size_t)t * HID);
    float ss = 0.f;
    for (int i = threadIdx.x; i < HID / 4; i += 256) {
        float4 v = xr[i];
        ss += v.x * v.x + v.y * v.y + v.z * v.z + v.w * v.w;
    }
    __shared__ float red[8];
    for (int off = 16; off; off >>= 1) ss += __shfl_xor_sync(0xffffffffu, ss, off);
    if ((threadIdx.x & 31) == 0) red[threadIdx.x >> 5] = ss;
    __syncthreads();
    if (threadIdx.x < 32) {
        float v = (threadIdx.x < 8) ? red[threadIdx.x] : 0.f;
        for (int off = 4; off; off >>= 1) v += __shfl_xor_sync(0xffffffffu, v, off);
        if (threadIdx.x == 0) red[0] = v;
    }
    __syncthreads();
    const float r = rsqrtf(red[0] / (float)HID + 1e-5f);

    const int mblk = t >> 7, mt = (t >> 4) & 7;
    const int lbase = (t & 7) * 4, jbase = (t >> 3) & 1;
    const float2* x2 = reinterpret_cast<const float2*>(x + (size_t)t * HID);
    const float2* s2 = reinterpret_cast<const float2*>(scale);
    for (int idx = threadIdx.x; idx < HID / 2; idx += 256) {
        const int k = idx * 2, kc = k >> 4, kin = k & 15;
        const int l = lbase + ((kin & 7) >> 1);
        const int j = jbase + ((kin >> 3) << 1);
        float2 v = x2[idx], sc = s2[idx];
        __half2 h = __floats2half2_rn(v.x * r * sc.x, v.y * r * sc.y);
        Ap[(((size_t)(mblk * KC1 + kc) * 8 + mt) * 32 + l) * 4 + j] =
            *reinterpret_cast<unsigned*>(&h);
    }
}

// ---------------- YaRN RoPE cos/sin table ----------------
__global__ void rope_table_kernel(const int* __restrict__ positions,
                                  float* __restrict__ gcos,
                                  float* __restrict__ gsin)
{
    const int t = blockIdx.x;
    const int i = threadIdx.x;  // 0..31
    const double pos = (double)positions[t];
    const double TWO_PI = 6.283185307179586476925286766559;
    const double BASE = 150000.0;
    const double freq = pow(BASE, (2.0 * i) / 64.0);
    const double conc = 0.1 * log(32.0) + 1.0;
    const double lo = 32.0 * log(4096.0 / (32.0 * TWO_PI)) / log(BASE);
    const double hi = 32.0 * log(4096.0 / (1.0 * TWO_PI)) / log(BASE);
    const double interp = 1.0 / (32.0 * freq);
    const double extrap = 1.0 / freq;
    double ramp = ((double)i - lo) / (hi - lo);
    ramp = fmin(fmax(ramp, 0.0), 1.0);
    const double mask = 1.0 - ramp;
    const double inv = interp * (1.0 - mask) + extrap * mask;
    const double ang = pos * inv;
    gcos[t * 32 + i] = (float)(cos(ang) * conc);
    gsin[t * 32 + i] = (float)(sin(ang) * conc);
}

// ================= fp16 mma.sync GEMM, 128x64 tile, 4-stage cp.async =================
// 128 threads (4 warps, 2x2), warp tile 64x32, m16n8k16.
__device__ __forceinline__ void cp16(uint32_t dst, const void* src)
{
    asm volatile("cp.async.cg.shared.global [%0], [%1], 16;"
                 :: "r"(dst), "l"(src) : "memory");
}
#define CP_COMMIT() asm volatile("cp.async.commit_group;" ::: "memory")
#define CP_WAIT2()  asm volatile("cp.async.wait_group 2;" ::: "memory")

#define MMA_F16(d, a, b) \
    asm volatile("mma.sync.aligned.m16n8k16.row.col.f32.f16.f16.f32 " \
                 "{%0,%1,%2,%3},{%4,%5,%6,%7},{%8,%9},{%0,%1,%2,%3};" \
                 : "+f"((d)[0]), "+f"((d)[1]), "+f"((d)[2]), "+f"((d)[3]) \
                 : "r"((a).x), "r"((a).y), "r"((a).z), "r"((a).w), \
                   "r"((b).x), "r"((b).y))

#define HSTAGES 4
// per stage: A 2048 u32 (8KB) + B 1024 u32 (4KB) = 12KB
#define HGEMM_SMEM (HSTAGES * 3072 * 4)

__global__ void __launch_bounds__(128)
hgemm_kernel(int M, int N, int K,
             const unsigned* __restrict__ Ap,
             const unsigned* __restrict__ Bp,
             const float* __restrict__ bias,
             const float* __restrict__ resid,
             float* __restrict__ C)
{
    extern __shared__ unsigned hsm[];

    const int KC = K >> 4;
    const int tid = threadIdx.x, lane = tid & 31, wid = tid >> 5;
    const int wm = wid >> 1, wn = wid & 1;
    const int mblk = blockIdx.y;
    const int nb64 = blockIdx.x;
    const int nb128 = nb64 >> 1, nhalf = nb64 & 1;
    const unsigned* Abase = Ap + (size_t)mblk * KC * 1024;
    const unsigned* Bbase = Bp + (size_t)nb128 * KC * 1024 + nhalf * 512;

    float acc[4][4][4];
#pragma unroll
    for (int i = 0; i < 4; i++)
#pragma unroll
        for (int j = 0; j < 4; j++)
#pragma unroll
            for (int q = 0; q < 4; q++) acc[i][j][q] = 0.f;

    const uint32_t sbase = (uint32_t)__cvta_generic_to_shared(hsm);
    const int nch = K / 32;

#define ISSUE_COPY(ch, s)                                                     \
    do {                                                                      \
        const unsigned* asrc = Abase + (size_t)(ch) * 2048;                   \
        uint32_t da = sbase + (s) * 12288;                                    \
        uint32_t db = da + 8192;                                              \
        cp16(da + tid * 16, asrc + tid * 4);                                  \
        cp16(da + (tid + 128) * 16, asrc + (tid + 128) * 4);                  \
        cp16(da + (tid + 256) * 16, asrc + (tid + 256) * 4);                  \
        cp16(da + (tid + 384) * 16, asrc + (tid + 384) * 4);                  \
        cp16(db + tid * 16,                                                   \
             Bbase + (size_t)(2 * (ch)) * 1024 + tid * 4);                    \
        cp16(db + 2048 + tid * 16,                                            \
             Bbase + (size_t)(2 * (ch) + 1) * 1024 + tid * 4);                \
    } while (0)

    ISSUE_COPY(0, 0); CP_COMMIT();
    ISSUE_COPY(1, 1); CP_COMMIT();
    ISSUE_COPY(2, 2); CP_COMMIT();

    for (int ch = 0; ch < nch; ch++) {
        CP_WAIT2();
        __syncthreads();

        if (ch + 3 < nch) ISSUE_COPY(ch + 3, (ch + 3) & 3);
        CP_COMMIT();

        const int st = ch & 3;
        const unsigned* Ast = hsm + (size_t)st * 3072;
        const unsigned* Bst = Ast + 2048;
#pragma unroll
        for (int ks = 0; ks < 2; ks++) {
            uint4 af[4];
            uint2 bf[4];
            const unsigned* ab = &Ast[ks * 1024 + wm * 512 + lane * 4];
            const unsigned* bb = &Bst[ks * 512 + wn * 256 + lane * 2];
#pragma unroll
            for (int mt = 0; mt < 4; mt++)
                af[mt] = *reinterpret_cast<const uint4*>(ab + mt * 128);
#pragma unroll
            for (int nt = 0; nt < 4; nt++)
                bf[nt] = *reinterpret_cast<const uint2*>(bb + nt * 64);
#pragma unroll
            for (int mt = 0; mt < 4; mt++)
#pragma unroll
                for (int nt = 0; nt < 4; nt++)
                    MMA_F16(acc[mt][nt], af[mt], bf[nt]);
        }
    }

    // epilogue: N is a multiple of 64 for both GEMMs -> no column guard needed
    const int m0 = mblk * 128 + wm * 64;
    const int n0 = nb64 * 64 + wn * 32;
#pragma unroll
    for (int mt = 0; mt < 4; mt++) {
        const int r = m0 + mt * 16 + (lane >> 2);
#pragma unroll
        for (int nt = 0; nt < 4; nt++) {
            const int c = n0 + nt * 8 + ((lane & 3) << 1);
            const float2 b = *reinterpret_cast<const float2*>(&bias[c]);
            float2 o0 = make_float2(acc[mt][nt][0] + b.x, acc[mt][nt][1] + b.y);
            float2 o1 = make_float2(acc[mt][nt][2] + b.x, acc[mt][nt][3] + b.y);
            const size_t i0 = (size_t)r * N + c;
            const size_t i1 = i0 + (size_t)8 * N;
            if (resid) {
                float2 e0 = *reinterpret_cast<const float2*>(&resid[i0]);
                float2 e1 = *reinterpret_cast<const float2*>(&resid[i1]);
                o0.x += e0.x; o0.y += e0.y;
                o1.x += e1.x; o1.y += e1.y;
            }
            *reinterpret_cast<float2*>(&C[i0]) = o0;
            *reinterpret_cast<float2*>(&C[i1]) = o1;
        }
    }
}

// ================= tensor-core sliding-window attention =================
// Fused: RoPE on Q/K at smem-load time; epilogue emits permuted fp16 A for gemm2.
// grid (kvh, qtile): 16 queries/block, 144-key window, 256 thr, warp = head.
// k0 = qt0 - 128: jl in [0,144); allowed for query q: jl > q && jl <= q+128.
#define TQ 16
#define NKEY 144
#define NT_S 18              // score n8 tiles
#define KT_P 9               // PV k16 tiles
#define QPAD 72              // halves per Q/K row
#define VPAD 152             // halves per Vt row
#define ATTN_SMEM ((128 * QPAD + NKEY * QPAD + 64 * VPAD) * 2)

__global__ void __launch_bounds__(256)
attn_mma_kernel(const float* __restrict__ qkv,
                const float* __restrict__ gcos,
                const float* __restrict__ gsin,
                const float* __restrict__ sinks,
                unsigned* __restrict__ Ap2)
{
    extern __shared__ __half asmem[];
    __half* Qs = asmem;                       // [128][QPAD]
    __half* Ks = Qs + 128 * QPAD;             // [NKEY][QPAD]
    __half* Vt = Ks + NKEY * QPAD;            // [64][VPAD]

    const int kvh = blockIdx.x;
    const int qt0 = blockIdx.y * TQ;
    const int k0 = qt0 - WIN;
    const bool full = (k0 >= 0);              // uniform: all keys valid
    const int tid = threadIdx.x;
    const int lane = tid & 31;
    const int wid = tid >> 5;                 // head within group

    // ---- load Q with fused RoPE ----
#pragma unroll
    for (int it = 0; it < 4; it++) {
        const int idx = tid + it * 256;       // 0..1023
        const int row = idx >> 3;
        const int c4 = (idx & 7) * 4;
        const int h = row >> 4, q = row & 15;
        const int t = qt0 + q;
        const float* src = &qkv[(size_t)t * QKV_N + (size_t)(kvh * 8 + h) * DH];
        float4 x1 = *reinterpret_cast<const float4*>(&src[c4]);
        float4 x2 = *reinterpret_cast<const float4*>(&src[c4 + 32]);
        float4 cs = *reinterpret_cast<const float4*>(&gcos[t * 32 + c4]);
        float4 sn = *reinterpret_cast<const float4*>(&gsin[t * 32 + c4]);
        __half* d1 = &Qs[row * QPAD + c4];
        __half* d2 = d1 + 32;
        d1[0] = __float2half_rn(x1.x * cs.x - x2.x * sn.x);
        d1[1] = __float2half_rn(x1.y * cs.y - x2.y * sn.y);
        d1[2] = __float2half_rn(x1.z * cs.z - x2.z * sn.z);
        d1[3] = __float2half_rn(x1.w * cs.w - x2.w * sn.w);
        d2[0] = __float2half_rn(x2.x * cs.x + x1.x * sn.x);
        d2[1] = __float2half_rn(x2.y * cs.y + x1.y * sn.y);
        d2[2] = __float2half_rn(x2.z * cs.z + x1.z * sn.z);
        d2[3] = __float2half_rn(x2.w * cs.w + x1.w * sn.w);
    }
    // ---- load K with fused RoPE ----
#pragma unroll
    for (int it = 0; it < 5; it++) {
        const int idx = tid + it * 256;       // 0..1151
        if (idx < NKEY * 8) {
            const int kk = idx >> 3;
            const int c4 = (idx & 7) * 4;
            const int j = k0 + kk;
            __half* d1 = &Ks[kk * QPAD + c4];
            __half* d2 = d1 + 32;
            if (full || j >= 0) {
                const float* src = &qkv[(size_t)j * QKV_N + K_OFF + (size_t)kvh * DH];
                float4 x1 = *reinterpret_cast<const float4*>(&src[c4]);
                float4 x2 = *reinterpret_cast<const float4*>(&src[c4 + 32]);
                float4 cs = *reinterpret_cast<const float4*>(&gcos[j * 32 + c4]);
                float4 sn = *reinterpret_cast<const float4*>(&gsin[j * 32 + c4]);
                d1[0] = __float2half_rn(x1.x * cs.x - x2.x * sn.x);
                d1[1] = __float2half_rn(x1.y * cs.y - x2.y * sn.y);
                d1[2] = __float2half_rn(x1.z * cs.z - x2.z * sn.z);
                d1[3] = __float2half_rn(x1.w * cs.w - x2.w * sn.w);
                d2[0] = __float2half_rn(x2.x * cs.x + x1.x * sn.x);
                d2[1] = __float2half_rn(x2.y * cs.y + x1.y * sn.y);
                d2[2] = __float2half_rn(x2.z * cs.z + x1.z * sn.z);
                d2[3] = __float2half_rn(x2.w * cs.w + x1.w * sn.w);
            } else {
                const __half z = __float2half_rn(0.f);
                d1[0] = z; d1[1] = z; d1[2] = z; d1[3] = z;
                d2[0] = z; d2[1] = z; d2[2] = z; d2[3] = z;
            }
        }
    }
    // ---- load V transposed: Vt[d][key] ----
#pragma unroll
    for (int it = 0; it < 9; it++) {
        const int idx = tid + it * 256;
        const int kk = idx >> 4;
        const int c4 = (idx & 15) * 4;
        const int j = k0 + kk;
        float4 v = (full || j >= 0)
            ? *reinterpret_cast<const float4*>(
                  &qkv[(size_t)j * QKV_N + V_OFF + (size_t)kvh * DH + c4])
            : make_float4(0.f, 0.f, 0.f, 0.f);
        Vt[(c4 + 0) * VPAD + kk] = __float2half_rn(v.x);
        Vt[(c4 + 1) * VPAD + kk] = __float2half_rn(v.y);
        Vt[(c4 + 2) * VPAD + kk] = __float2half_rn(v.z);
        Vt[(c4 + 3) * VPAD + kk] = __float2half_rn(v.w);
    }
    __syncthreads();

    // ---- Q fragments (m16k16 x4 over K=64) ----
    const __half* qrow = &Qs[(wid * 16 + (lane >> 2)) * QPAD];
    uint4 af[4];
#pragma unroll
    for (int kt = 0; kt < 4; kt++) {
        const int col = kt * 16 + ((lane & 3) << 1);
        af[kt].x = *reinterpret_cast<const unsigned*>(&qrow[col]);
        af[kt].y = *reinterpret_cast<const unsigned*>(&qrow[8 * QPAD + col]);
        af[kt].z = *reinterpret_cast<const unsigned*>(&qrow[col + 8]);
        af[kt].w = *reinterpret_cast<const unsigned*>(&qrow[8 * QPAD + col + 8]);
    }

    // ---- scores ----
    float sacc[NT_S][4];
#pragma unroll
    for (int nt = 0; nt < NT_S; nt++)
#pragma unroll
        for (int c = 0; c < 4; c++) sacc[nt][c] = 0.f;

#pragma unroll
    for (int nt = 0; nt < NT_S; nt++) {
        const __half* krow = &Ks[(nt * 8 + (lane >> 2)) * QPAD];
#pragma unroll
        for (int kt = 0; kt < 4; kt++) {
            uint2 b;
            const int col = kt * 16 + ((lane & 3) << 1);
            b.x = *reinterpret_cast<const unsigned*>(&krow[col]);
            b.y = *reinterpret_cast<const unsigned*>(&krow[col + 8]);
            MMA_F16(sacc[nt], af[kt], b);
        }
    }

    // ---- mask + softmax (rows q_a = lane>>2, q_b = q_a+8) ----
    const int q_a = lane >> 2, q_b = q_a + 8;
    const float sink = sinks[kvh * 8 + wid];
    float mxa = -1e30f, mxb = -1e30f;
#pragma unroll
    for (int nt = 0; nt < NT_S; nt++) {
#pragma unroll
        for (int c = 0; c < 2; c++) {
            const int jl = nt * 8 + ((lane & 3) << 1) + c;
            const bool in0 = full || (k0 + jl >= 0);
            const bool oka = in0 && (jl > q_a) && (jl <= q_a + 128);
            const bool okb = in0 && (jl > q_b) && (jl <= q_b + 128);
            const float va = oka ? sacc[nt][c] * 0.125f : -1e30f;
            const float vb = okb ? sacc[nt][c + 2] * 0.125f : -1e30f;
            sacc[nt][c] = va; sacc[nt][c + 2] = vb;
            mxa = fmaxf(mxa, va); mxb = fmaxf(mxb, vb);
        }
    }
    mxa = fmaxf(mxa, __shfl_xor_sync(0xffffffffu, mxa, 1));
    mxa = fmaxf(mxa, __shfl_xor_sync(0xffffffffu, mxa, 2));
    mxb = fmaxf(mxb, __shfl_xor_sync(0xffffffffu, mxb, 1));
    mxb = fmaxf(mxb, __shfl_xor_sync(0xffffffffu, mxb, 2));
    const float Ma = fmaxf(mxa, sink), Mb = fmaxf(mxb, sink);

    unsigned pha[NT_S], phb[NT_S];
    float suma = 0.f, sumb = 0.f;
#pragma unroll
    for (int nt = 0; nt < NT_S; nt++) {
        const float p0 = __expf(sacc[nt][0] - Ma);
        const float p1 = __expf(sacc[nt][1] - Ma);
        const float p2 = __expf(sacc[nt][2] - Mb);
        const float p3 = __expf(sacc[nt][3] - Mb);
        suma += p0 + p1; sumb += p2 + p3;
        __half2 ha = __floats2half2_rn(p0, p1);
        __half2 hb = __floats2half2_rn(p2, p3);
        pha[nt] = *reinterpret_cast<unsigned*>(&ha);
        phb[nt] = *reinterpret_cast<unsigned*>(&hb);
    }
    suma += __shfl_xor_sync(0xffffffffu, suma, 1);
    suma += __shfl_xor_sync(0xffffffffu, suma, 2);
    sumb += __shfl_xor_sync(0xffffffffu, sumb, 1);
    sumb += __shfl_xor_sync(0xffffffffu, sumb, 2);
    const float inva = 1.f / (suma + __expf(sink - Ma));
    const float invb = 1.f / (sumb + __expf(sink - Mb));

    // ---- PV: 9 k16-tiles x 8 n8-tiles ----
    float oacc[8][4];
#pragma unroll
    for (int nt = 0; nt < 8; nt++)
#pragma unroll
        for (int c = 0; c < 4; c++) oacc[nt][c] = 0.f;

#pragma unroll
    for (int kt = 0; kt < KT_P; kt++) {
        uint4 a;
        a.x = pha[2 * kt];
        a.y = phb[2 * kt];
        a.z = pha[2 * kt + 1];
        a.w = phb[2 * kt + 1];
        const int kcol = kt * 16 + ((lane & 3) << 1);
#pragma unroll
        for (int nt = 0; nt < 8; nt++) {
            const __half* vrow = &Vt[(nt * 8 + (lane >> 2)) * VPAD];
            uint2 b;
            b.x = *reinterpret_cast<const unsigned*>(&vrow[kcol]);
            b.y = *reinterpret_cast<const unsigned*>(&vrow[kcol + 8]);
            MMA_F16(oacc[nt], a, b);
        }
    }

    // ---- epilogue: emit permuted fp16 A for gemm2 directly ----
    const int mblk = qt0 >> 7, mt = (qt0 >> 4) & 7;
    const int head = kvh * 8 + wid;
#pragma unroll
    for (int kcp = 0; kcp < 4; kcp++) {
        const int nt0 = 2 * kcp, nt1 = 2 * kcp + 1;
        __half2 h0 = __floats2half2_rn(oacc[nt0][0] * inva, oacc[nt0][1] * inva);
        __half2 h1 = __floats2half2_rn(oacc[nt0][2] * invb, oacc[nt0][3] * invb);
        __half2 h2 = __floats2half2_rn(oacc[nt1][0] * inva, oacc[nt1][1] * inva);
        __half2 h3 = __floats2half2_rn(oacc[nt1][2] * invb, oacc[nt1][3] * invb);
        const int kc = head * 4 + kcp;
        const size_t base = (((size_t)(mblk * KC2 + kc) * 8 + mt) * 32 + lane) * 4;
        *reinterpret_cast<uint4*>(&Ap2[base]) =
            make_uint4(*reinterpret_cast<unsigned*>(&h0),
                       *reinterpret_cast<unsigned*>(&h1),
                       *reinterpret_cast<unsigned*>(&h2),
                       *reinterpret_cast<unsigned*>(&h3));
    }
}

// ---------------- launch ----------------
extern "C" void kernel_launch(void* const* d_in, const int* in_sizes, int n_in,
                              void* d_out, int out_size)
{
    const float* hidden     = (const float*)d_in[0];
    const int*   positions  = (const int*)d_in[1];
    const float* norm_scale = (const float*)d_in[2];
    const float* w_qkv      = (const float*)d_in[3];
    const float* b_qkv      = (const float*)d_in[4];
    const float* w_out      = (const float*)d_in[5];
    const float* b_out      = (const float*)d_in[6];
    const float* sinks      = (const float*)d_in[7];
    float* out = (float*)d_out;

    float *qkv, *gcos, *gsin;
    unsigned *Ap1, *Ap2, *Bp1, *Bp2;
    cudaGetSymbolAddress((void**)&qkv, g_qkv);
    cudaGetSymbolAddress((void**)&gcos, g_cos);
    cudaGetSymbolAddress((void**)&gsin, g_sin);
    cudaGetSymbolAddress((void**)&Ap1, g_Ap1);
    cudaGetSymbolAddress((void**)&Ap2, g_Ap2);
    cudaGetSymbolAddress((void**)&Bp1, g_Bp1);
    cudaGetSymbolAddress((void**)&Bp2, g_Bp2);

    cudaFuncSetAttribute(hgemm_kernel,
                         cudaFuncAttributeMaxDynamicSharedMemorySize, HGEMM_SMEM);
    cudaFuncSetAttribute(attn_mma_kernel,
                         cudaFuncAttributeMaxDynamicSharedMemorySize, ATTN_SMEM);

    // 1: rope table
    rope_table_kernel<<<T_SEQ, 32>>>(positions, gcos, gsin);
    // 2: convert w_qkv
    convB_kernel<<<dim3(NBLK1, KC1), 256>>>(w_qkv, Bp1, HID, QKV_N, KC1);
    // 3: rmsnorm + convert A1
    rmsnorm_convA_kernel<<<T_SEQ, 256>>>(hidden, norm_scale, Ap1);
    // 4 (profiled slot): qkv GEMM (M=1024, N=5120, K=2880), 128x64 tiles
    hgemm_kernel<<<dim3(QKV_N / 64, T_SEQ / 128), 128, HGEMM_SMEM>>>(
        T_SEQ, QKV_N, HID, Ap1, Bp1, b_qkv, nullptr, qkv);
    // 5: attention (fused rope + permuted fp16 output)
    attn_mma_kernel<<<dim3(KVH, T_SEQ / TQ), 256, ATTN_SMEM>>>(
        qkv, gcos, gsin, sinks, Ap2);
    // 6: convert w_out
    convB_kernel<<<dim3(NBLK2, KC2), 256>>>(w_out, Bp2, ATT_N, HID, KC2);
    // 7: out GEMM + residual (M=1024, N=2880, K=4096), 128x64 tiles
    hgemm_kernel<<<dim3(HID / 64, T_SEQ / 128), 128, HGEMM_SMEM>>>(
        T_SEQ, HID, ATT_N, Ap2, Bp2, b_out, hidden, out);
}